// round 14
// baseline (speedup 1.0000x reference)
#include <cuda_runtime.h>

#define Bn 16
#define Cn 64
#define Hn 256
#define Wn 256
#define PHn 128
#define PWn 128
#define CH_STRIDE (Hn * Wn)      // 65536 floats between channels (feature)
#define PCH_STRIDE (PHn * PWn)   // 16384 cells between channels (pooled)

typedef unsigned long long u64;

// pooled stored DUPLICATED: each cell is float2 {v, v}  (128 MiB scratch)
__device__ float2 g_pool2[Bn * Cn * PHn * PWn];

// ---- f32x2 helpers -------------------------------------------------------
__device__ __forceinline__ void fma2(u64& d, u64 a, u64 b) {
    asm("fma.rn.f32x2 %0, %1, %2, %0;" : "+l"(d) : "l"(a), "l"(b));
}
__device__ __forceinline__ float2 unpack2(u64 v) {
    float2 r;
    asm("mov.b64 {%0, %1}, %2;" : "=f"(r.x), "=f"(r.y) : "l"(v));
    return r;
}

// ---- cp.async helpers ----------------------------------------------------
__device__ __forceinline__ void cp_async8(unsigned int smem_dst, const void* src) {
    asm volatile("cp.async.ca.shared.global [%0], [%1], 8;" :: "r"(smem_dst), "l"(src));
}
__device__ __forceinline__ void cp_async16(unsigned int smem_dst, const void* src) {
    asm volatile("cp.async.cg.shared.global [%0], [%1], 16;" :: "r"(smem_dst), "l"(src));
}
__device__ __forceinline__ void cp_commit() { asm volatile("cp.async.commit_group;"); }
__device__ __forceinline__ void cp_wait0()  { asm volatile("cp.async.wait_group 0;"); }

// ---------------------------------------------------------------------------
// Pass 1: avg_pool2d k=3 s=2 pad=1 (count_include_pad: always /9).
// Writes each pooled value DUPLICATED {v,v} (two STG.128 per thread).
// ---------------------------------------------------------------------------
__global__ __launch_bounds__(256) void pool_kernel(const float* __restrict__ feat) {
    int idx = blockIdx.x * 256 + threadIdx.x;
    int pwq = idx & 31;
    int t   = idx >> 5;
    int ph  = t & 127;
    int bc  = t >> 7;
    const float* src = feat + (size_t)bc * (Hn * Wn);
    int c0 = pwq << 3;

    float s0 = 0.f, s1 = 0.f, s2 = 0.f, s3 = 0.f;
    int rbase = 2 * ph - 1;
#pragma unroll
    for (int rr = 0; rr < 3; rr++) {
        int r = rbase + rr;
        if (r < 0) continue;
        const float* row = src + r * Wn;
        float left = (c0 > 0) ? __ldcs(row + c0 - 1) : 0.f;
        float4 a  = __ldcs(reinterpret_cast<const float4*>(row + c0));
        float4 b4 = __ldcs(reinterpret_cast<const float4*>(row + c0 + 4));
        s0 += left + a.x  + a.y;
        s1 += a.y  + a.z  + a.w;
        s2 += a.w  + b4.x + b4.y;
        s3 += b4.y + b4.z + b4.w;
    }
    const float inv9 = 1.0f / 9.0f;
    s0 *= inv9; s1 *= inv9; s2 *= inv9; s3 *= inv9;

    float4* dst = reinterpret_cast<float4*>(
        g_pool2 + (size_t)bc * PCH_STRIDE + ph * PWn + (pwq << 2));
    dst[0] = make_float4(s0, s0, s1, s1);
    dst[1] = make_float4(s2, s2, s3, s3);
}

// ---------------------------------------------------------------------------
// Pass 2: diff + fused P2. Block = 16x16 quads = 32x32 output tile.
// Feature 32x32 tile + DUPLICATED pooled halo (18x18 float2 cells) staged per
// 4-channel chunk via cp.async, double-buffered (dynamic smem, 54.8 KB).
// Every f32x2 broadcast operand is ONE aligned LDS.64 — zero MOV duplication.
// Safe pipeline: wait0 -> sync -> stage(next) -> compute(cur).
// jnp.roll wrap via &127 in precomputed gather offsets.
// ---------------------------------------------------------------------------
#define CHUNK  4
#define HALO   324                 // 18*18 halo cells
#define FROW   32                  // feature smem row (floats)
#define FCH    (32 * FROW)         // 1024 floats per staged channel
#define FBUF   (CHUNK * FCH)       // 4096 floats per feature buffer
#define HBUF   (CHUNK * HALO)      // 1296 float2 per halo buffer
#define NITER  (Cn / CHUNK)        // 16
#define SMEM_BYTES (2 * FBUF * 4 + 2 * HBUF * 8 + HALO * 4)   // 54,800 B

__global__ __launch_bounds__(256, 4) void diff_kernel(const float* __restrict__ feat,
                                                      float* __restrict__ out) {
    extern __shared__ __align__(16) char smem_raw[];
    float*  sfeat = reinterpret_cast<float*>(smem_raw);                 // 2*FBUF
    float2* shalo = reinterpret_cast<float2*>(smem_raw + 2 * FBUF * 4); // 2*HBUF
    float*  sP2   = reinterpret_cast<float*>(smem_raw + 2 * FBUF * 4 + 2 * HBUF * 8);

    int b   = blockIdx.z;
    int ph0 = blockIdx.y << 4;
    int pw0 = blockIdx.x << 4;
    int tid = threadIdx.x;
    int qx  = tid & 15, qy = tid >> 4;

    const float*  fimg = feat + (size_t)b * Cn * CH_STRIDE;
    const float2* pimg = g_pool2 + (size_t)b * Cn * PCH_STRIDE;
    unsigned int sfeat_a = (unsigned int)__cvta_generic_to_shared(sfeat);
    unsigned int shalo_a = (unsigned int)__cvta_generic_to_shared(shalo);

    // ---- feature staging constants: 1 cp16 per channel per thread ----
    int frow = tid >> 3;
    int fcol = (tid & 7) << 2;
    const float* fsrc0 = fimg + (size_t)((ph0 << 1) + frow) * Wn + (pw0 << 1) + fcol;
    unsigned int fdst0 = sfeat_a + (unsigned)(frow * FROW + fcol) * 4;

    // ---- halo gather offsets (cell tid always; cell tid+256 if tid<68) ----
    int i0 = tid / 18, j0 = tid - i0 * 18;
    int gofs0 = (((ph0 - 1 + i0) & 127) << 7) + ((pw0 - 1 + j0) & 127);
    int cell1 = tid + 256;
    bool has1 = (cell1 < HALO);
    int i1 = cell1 / 18, j1 = cell1 - i1 * 18;
    int gofs1 = (((ph0 - 1 + i1) & 127) << 7) + ((pw0 - 1 + j1) & 127);

    // cc is a CHANNEL BASE
    auto stage = [&](int buf, int cc) {
        unsigned int fd = fdst0 + buf * (FBUF * 4);
        const float* fs = fsrc0 + (size_t)cc * CH_STRIDE;
#pragma unroll
        for (int m = 0; m < CHUNK; m++) {
            cp_async16(fd + m * (FCH * 4), fs);
            fs += CH_STRIDE;
        }
        unsigned int hd = shalo_a + buf * (HBUF * 8);
        const float2* hs = pimg + (size_t)cc * PCH_STRIDE;
#pragma unroll
        for (int c = 0; c < CHUNK; c++) {
            cp_async8(hd + (unsigned)(c * HALO + tid) * 8, hs + gofs0);
            if (has1) cp_async8(hd + (unsigned)(c * HALO + cell1) * 8, hs + gofs1);
            hs += PCH_STRIDE;
        }
        cp_commit();
    };

    // ---- accumulators ----
    u64 z = 0;
    u64 cr01[8], cr23[8];
#pragma unroll
    for (int s = 0; s < 8; s++) { cr01[s] = z; cr23[s] = z; }
    u64 F2_01 = z, F2_23 = z;
    float p2acc0 = 0.f, p2acc1 = 0.f;
    int sbase = (qy + 1) * 18 + (qx + 1);
    int qoff  = (qy << 1) * FROW + (qx << 1);

    stage(0, 0);

    for (int it = 0; it < NITER; it++) {
        int cur = it & 1;
        cp_wait0();
        __syncthreads();               // chunk it visible; all reads of buffer
                                       // 1-cur (iteration it-1) complete
        if (it + 1 < NITER) stage(1 - cur, (it + 1) * CHUNK);

        const float*  fbuf = sfeat + cur * FBUF;
        const float2* hbuf = shalo + cur * HBUF;

        // ---- P2 fold (register-carried; reads .x of dup cells) ----
#pragma unroll
        for (int c = 0; c < CHUNK; c++) {
            float v = hbuf[c * HALO + tid].x;
            p2acc0 += v * v;
        }
        if (has1) {
#pragma unroll
            for (int c = 0; c < CHUNK; c++) {
                float v = hbuf[c * HALO + cell1].x;
                p2acc1 += v * v;
            }
        }

        // ---- quad accumulation: every operand one LDS.64, zero bcast MOVs ----
#pragma unroll
        for (int c = 0; c < CHUNK; c++) {
            const float* fp = fbuf + c * FCH + qoff;
            u64 f01 = *reinterpret_cast<const u64*>(fp);
            u64 f23 = *reinterpret_cast<const u64*>(fp + FROW);

            const float2* hc = hbuf + c * HALO + sbase;
            u64 pp0 = *reinterpret_cast<const u64*>(hc - 19);
            u64 pp1 = *reinterpret_cast<const u64*>(hc - 18);
            u64 pp2 = *reinterpret_cast<const u64*>(hc - 17);
            u64 pp3 = *reinterpret_cast<const u64*>(hc - 1);
            u64 pp4 = *reinterpret_cast<const u64*>(hc + 1);
            u64 pp5 = *reinterpret_cast<const u64*>(hc + 17);
            u64 pp6 = *reinterpret_cast<const u64*>(hc + 18);
            u64 pp7 = *reinterpret_cast<const u64*>(hc + 19);

            fma2(F2_01, f01, f01);
            fma2(F2_23, f23, f23);
            fma2(cr01[0], f01, pp0); fma2(cr23[0], f23, pp0);
            fma2(cr01[1], f01, pp1); fma2(cr23[1], f23, pp1);
            fma2(cr01[2], f01, pp2); fma2(cr23[2], f23, pp2);
            fma2(cr01[3], f01, pp3); fma2(cr23[3], f23, pp3);
            fma2(cr01[4], f01, pp4); fma2(cr23[4], f23, pp4);
            fma2(cr01[5], f01, pp5); fma2(cr23[5], f23, pp5);
            fma2(cr01[6], f01, pp6); fma2(cr23[6], f23, pp6);
            fma2(cr01[7], f01, pp7); fma2(cr23[7], f23, pp7);
        }
    }

    // ---- publish P2 tile ----
    __syncthreads();                   // all halo reads complete
    sP2[tid] = p2acc0;
    if (has1) sP2[cell1] = p2acc1;
    __syncthreads();

    float P2n[8];
    P2n[0] = sP2[sbase - 19]; P2n[1] = sP2[sbase - 18]; P2n[2] = sP2[sbase - 17];
    P2n[3] = sP2[sbase - 1];                             P2n[4] = sP2[sbase + 1];
    P2n[5] = sP2[sbase + 17]; P2n[6] = sP2[sbase + 18]; P2n[7] = sP2[sbase + 19];

    float2 F2p01 = unpack2(F2_01);
    float2 F2p23 = unpack2(F2_23);
    float F2arr[4] = {F2p01.x, F2p01.y, F2p23.x, F2p23.y};

    float res[4] = {-3.4e38f, -3.4e38f, -3.4e38f, -3.4e38f};
#pragma unroll
    for (int s = 0; s < 8; s++) {
        float2 c01 = unpack2(cr01[s]);
        float2 c23 = unpack2(cr23[s]);
        res[0] = fmaxf(res[0], F2arr[0] - 2.f * c01.x + P2n[s]);
        res[1] = fmaxf(res[1], F2arr[1] - 2.f * c01.y + P2n[s]);
        res[2] = fmaxf(res[2], F2arr[2] - 2.f * c23.x + P2n[s]);
        res[3] = fmaxf(res[3], F2arr[3] - 2.f * c23.y + P2n[s]);
    }

    int ph = ph0 + qy, pw = pw0 + qx;
    float* orow = out + (size_t)b * (Hn * Wn) + (ph << 1) * Wn + (pw << 1);
    *reinterpret_cast<float2*>(orow)      = make_float2(res[0], res[1]);
    *reinterpret_cast<float2*>(orow + Wn) = make_float2(res[2], res[3]);
}

// ---------------------------------------------------------------------------
extern "C" void kernel_launch(void* const* d_in, const int* in_sizes, int n_in,
                              void* d_out, int out_size) {
    const float* feat = (const float*)d_in[0];
    float* out = (float*)d_out;
    // dist is fixed at 1 by the problem's setup_inputs (d = 2)

    cudaFuncSetAttribute(diff_kernel,
                         cudaFuncAttributeMaxDynamicSharedMemorySize, SMEM_BYTES);

    pool_kernel<<<16384, 256>>>(feat);
    dim3 g(8, 8, Bn);
    diff_kernel<<<g, 256, SMEM_BYTES>>>(feat, out);
}

// round 15
// speedup vs baseline: 1.5027x; 1.5027x over previous
#include <cuda_runtime.h>

#define Bn 16
#define Cn 64
#define Hn 256
#define Wn 256
#define PHn 128
#define PWn 128
#define CH_STRIDE (Hn * Wn)      // 65536 floats between channels (feature)
#define PCH_STRIDE (PHn * PWn)   // 16384 floats between channels (pooled)

typedef unsigned long long u64;

// scratch (static __device__ — allocation-free per harness rules)
__device__ float g_pooled[Bn * Cn * PHn * PWn];  // 64 MiB

// ---- f32x2 helpers -------------------------------------------------------
__device__ __forceinline__ void fma2(u64& d, u64 a, u64 b) {
    asm("fma.rn.f32x2 %0, %1, %2, %0;" : "+l"(d) : "l"(a), "l"(b));
}
__device__ __forceinline__ u64 bcast2(float v) {
    u64 r;
    asm("mov.b64 %0, {%1, %2};" : "=l"(r) : "f"(v), "f"(v));
    return r;
}
__device__ __forceinline__ float2 unpack2(u64 v) {
    float2 r;
    asm("mov.b64 {%0, %1}, %2;" : "=f"(r.x), "=f"(r.y) : "l"(v));
    return r;
}
__device__ __forceinline__ u64 as_u64(float2 v) {
    u64 r;
    asm("mov.b64 %0, {%1, %2};" : "=l"(r) : "f"(v.x), "f"(v.y));
    return r;
}

// ---- cp.async helpers ----------------------------------------------------
__device__ __forceinline__ void cp_async4(unsigned int smem_dst, const float* src) {
    asm volatile("cp.async.ca.shared.global [%0], [%1], 4;" :: "r"(smem_dst), "l"(src));
}
__device__ __forceinline__ void cp_async16(unsigned int smem_dst, const float* src) {
    asm volatile("cp.async.cg.shared.global [%0], [%1], 16;" :: "r"(smem_dst), "l"(src));
}
__device__ __forceinline__ void cp_commit()  { asm volatile("cp.async.commit_group;"); }
__device__ __forceinline__ void cp_wait1()   { asm volatile("cp.async.wait_group 1;"); }
__device__ __forceinline__ void cp_wait0()   { asm volatile("cp.async.wait_group 0;"); }

// ---------------------------------------------------------------------------
// Pass 1: avg_pool2d k=3 s=2 pad=1 (count_include_pad: always /9).
// ~84% DRAM — near unique-traffic roofline; unchanged from the champion.
// ---------------------------------------------------------------------------
__global__ __launch_bounds__(256) void pool_kernel(const float* __restrict__ feat) {
    int idx = blockIdx.x * 256 + threadIdx.x;
    int pwq = idx & 31;
    int t   = idx >> 5;
    int ph  = t & 127;
    int bc  = t >> 7;
    const float* src = feat + (size_t)bc * (Hn * Wn);
    int c0 = pwq << 3;

    float s0 = 0.f, s1 = 0.f, s2 = 0.f, s3 = 0.f;
    int rbase = 2 * ph - 1;
#pragma unroll
    for (int rr = 0; rr < 3; rr++) {
        int r = rbase + rr;
        if (r < 0) continue;
        const float* row = src + r * Wn;
        float left = (c0 > 0) ? __ldcs(row + c0 - 1) : 0.f;
        float4 a  = __ldcs(reinterpret_cast<const float4*>(row + c0));
        float4 b4 = __ldcs(reinterpret_cast<const float4*>(row + c0 + 4));
        s0 += left + a.x  + a.y;
        s1 += a.y  + a.z  + a.w;
        s2 += a.w  + b4.x + b4.y;
        s3 += b4.y + b4.z + b4.w;
    }
    const float inv9 = 1.0f / 9.0f;
    float4 o = make_float4(s0 * inv9, s1 * inv9, s2 * inv9, s3 * inv9);
    *reinterpret_cast<float4*>(g_pooled + (size_t)bc * PCH_STRIDE + ph * PWn + (pwq << 2)) = o;
}

// ---------------------------------------------------------------------------
// Pass 2: diff + fused P2. EXACT R5 champion structure:
//   - 16x16 quads = 32x32 output tile per 256-thread block
//   - per 4-channel chunk: cp.async double-buffered feature 32x32 tile (cp16)
//     + pooled 18x18 halo (cp4), stage(next) THEN cp_wait1, ONE sync per chunk
//   - f32x2 packed math with bcast2 broadcasts
// Changes vs R5 (local only):
//   - halo staging (src,dst) descriptors precomputed ONCE (kills ~800 ALU
//     instr/thread of per-chunk div/mod address math)
//   - P2 fold carried in registers (kills per-chunk sP2 LDS/STS round trip)
// ---------------------------------------------------------------------------
#define CHUNK   4
#define HALO    324                 // 18*18
#define FROW    32                  // feature smem row (floats)
#define FCH     (32 * FROW)         // 1024 floats per staged channel
#define NITER   (Cn / CHUNK)        // 16

__global__ __launch_bounds__(256, 4) void diff_kernel(const float* __restrict__ feat,
                                                      float* __restrict__ out) {
    __shared__ __align__(16) float sfeat[2][CHUNK * FCH];  // 32,768 B
    __shared__ float shalo[2][CHUNK * HALO];               // 10,368 B
    __shared__ float sP2[HALO];                            //  1,296 B

    int b   = blockIdx.z;
    int ph0 = blockIdx.y << 4;
    int pw0 = blockIdx.x << 4;
    int tid = threadIdx.x;
    int qx  = tid & 15, qy = tid >> 4;

    const float* fimg = feat + (size_t)b * Cn * CH_STRIDE;
    const float* pimg = g_pooled + (size_t)b * Cn * PCH_STRIDE;
    unsigned int sfeat_a = (unsigned int)__cvta_generic_to_shared(&sfeat[0][0]);
    unsigned int shalo_a = (unsigned int)__cvta_generic_to_shared(&shalo[0][0]);

    // ---- feature staging constants: 1 cp16 per channel per thread ----
    int frow = tid >> 3;
    int fcol = (tid & 7) << 2;
    const float* fsrc0 = fimg + (size_t)((ph0 << 1) + frow) * Wn + (pw0 << 1) + fcol;
    unsigned int fdst0 = sfeat_a + (unsigned)(frow * FROW + fcol) * 4;

    // ---- halo staging descriptors, precomputed ONCE (6 slots) ----
    int hsrc[6];
    unsigned int hdst[6];
    bool hok[6];
#pragma unroll
    for (int u = 0; u < 6; u++) {
        int k = tid + 256 * u;                 // 0..1535; need < 1296
        hok[u] = (k < CHUNK * HALO);
        int kk = hok[u] ? k : 0;
        int c = kk / HALO;
        int r = kk - c * HALO;
        int i = r / 18;
        int j = r - i * 18;
        int gr = (ph0 - 1 + i) & 127;
        int gc = (pw0 - 1 + j) & 127;
        hsrc[u] = c * PCH_STRIDE + (gr << 7) + gc;
        hdst[u] = (unsigned)kk * 4;
    }

    // ---- staging: one 4-channel chunk (feature tile + pooled halo) ----
    // cc is a CHANNEL BASE
    auto stage = [&](int buf, int cc) {
        unsigned int fd = fdst0 + buf * (CHUNK * FCH * 4);
        const float* fs = fsrc0 + (size_t)cc * CH_STRIDE;
#pragma unroll
        for (int m = 0; m < CHUNK; m++) {
            cp_async16(fd + m * (FCH * 4), fs);
            fs += CH_STRIDE;
        }
        unsigned int hd = shalo_a + buf * (CHUNK * HALO * 4);
        const float* pb = pimg + (size_t)cc * PCH_STRIDE;
#pragma unroll
        for (int u = 0; u < 6; u++)
            if (hok[u]) cp_async4(hd + hdst[u], pb + hsrc[u]);
        cp_commit();
    };

    // ---- accumulators ----
    u64 z = 0;
    u64 cr01[8], cr23[8];
#pragma unroll
    for (int s = 0; s < 8; s++) { cr01[s] = z; cr23[s] = z; }
    u64 F2_01 = z, F2_23 = z;
    float p2acc0 = 0.f, p2acc1 = 0.f;
    int cell1 = tid + 256;
    bool has1 = (cell1 < HALO);
    int sbase = (qy + 1) * 18 + (qx + 1);
    int qoff  = (qy << 1) * FROW + (qx << 1);

    stage(0, 0);

    for (int it = 0; it < NITER; it++) {
        int cur = it & 1;
        if (it + 1 < NITER) { stage(1 - cur, (it + 1) * CHUNK); cp_wait1(); }
        else                { cp_wait0(); }
        __syncthreads();                    // staged chunk visible to all

        const float* hbuf = &shalo[cur][0];
        const float* fbuf = &sfeat[cur][0];

        // ---- P2 fold over the staged halo (register-carried) ----
#pragma unroll
        for (int c = 0; c < CHUNK; c++) {
            float v = hbuf[c * HALO + tid];
            p2acc0 += v * v;
        }
        if (has1) {
#pragma unroll
            for (int c = 0; c < CHUNK; c++) {
                float v = hbuf[c * HALO + cell1];
                p2acc1 += v * v;
            }
        }

        // ---- quad accumulation (all operands from smem) ----
#pragma unroll
        for (int c = 0; c < CHUNK; c++) {
            const float* fp = fbuf + c * FCH + qoff;
            u64 f01 = as_u64(*reinterpret_cast<const float2*>(fp));
            u64 f23 = as_u64(*reinterpret_cast<const float2*>(fp + FROW));

            const float* hc = hbuf + c * HALO;
            float ps[8];
            ps[0] = hc[sbase - 19]; ps[1] = hc[sbase - 18]; ps[2] = hc[sbase - 17];
            ps[3] = hc[sbase - 1];                          ps[4] = hc[sbase + 1];
            ps[5] = hc[sbase + 17]; ps[6] = hc[sbase + 18]; ps[7] = hc[sbase + 19];

            fma2(F2_01, f01, f01);
            fma2(F2_23, f23, f23);
#pragma unroll
            for (int s = 0; s < 8; s++) {
                u64 pp = bcast2(ps[s]);
                fma2(cr01[s], f01, pp);
                fma2(cr23[s], f23, pp);
            }
        }
    }

    // ---- publish P2 tile ----
    __syncthreads();                        // all halo reads complete
    sP2[tid] = p2acc0;
    if (has1) sP2[cell1] = p2acc1;
    __syncthreads();

    float P2n[8];
    P2n[0] = sP2[sbase - 19]; P2n[1] = sP2[sbase - 18]; P2n[2] = sP2[sbase - 17];
    P2n[3] = sP2[sbase - 1];                             P2n[4] = sP2[sbase + 1];
    P2n[5] = sP2[sbase + 17]; P2n[6] = sP2[sbase + 18]; P2n[7] = sP2[sbase + 19];

    float2 F2p01 = unpack2(F2_01);
    float2 F2p23 = unpack2(F2_23);
    float F2arr[4] = {F2p01.x, F2p01.y, F2p23.x, F2p23.y};

    float res[4] = {-3.4e38f, -3.4e38f, -3.4e38f, -3.4e38f};
#pragma unroll
    for (int s = 0; s < 8; s++) {
        float2 c01 = unpack2(cr01[s]);
        float2 c23 = unpack2(cr23[s]);
        res[0] = fmaxf(res[0], F2arr[0] - 2.f * c01.x + P2n[s]);
        res[1] = fmaxf(res[1], F2arr[1] - 2.f * c01.y + P2n[s]);
        res[2] = fmaxf(res[2], F2arr[2] - 2.f * c23.x + P2n[s]);
        res[3] = fmaxf(res[3], F2arr[3] - 2.f * c23.y + P2n[s]);
    }

    int ph = ph0 + qy, pw = pw0 + qx;
    float* orow = out + (size_t)b * (Hn * Wn) + (ph << 1) * Wn + (pw << 1);
    *reinterpret_cast<float2*>(orow)      = make_float2(res[0], res[1]);
    *reinterpret_cast<float2*>(orow + Wn) = make_float2(res[2], res[3]);
}

// ---------------------------------------------------------------------------
extern "C" void kernel_launch(void* const* d_in, const int* in_sizes, int n_in,
                              void* d_out, int out_size) {
    const float* feat = (const float*)d_in[0];
    float* out = (float*)d_out;
    // dist is fixed at 1 by the problem's setup_inputs (d = 2)

    pool_kernel<<<16384, 256>>>(feat);
    dim3 g(8, 8, Bn);
    diff_kernel<<<g, 256>>>(feat, out);
}

// round 16
// speedup vs baseline: 1.5253x; 1.0151x over previous
#include <cuda_runtime.h>

#define Bn 16
#define Cn 64
#define Hn 256
#define Wn 256
#define PHn 128
#define PWn 128
#define CH_STRIDE (Hn * Wn)      // 65536 floats between channels (feature)
#define PCH_STRIDE (PHn * PWn)   // 16384 floats between channels (pooled)

typedef unsigned long long u64;

// scratch (static __device__ — allocation-free per harness rules)
__device__ float g_pooled[Bn * Cn * PHn * PWn];  // 64 MiB

// ---- f32x2 helpers -------------------------------------------------------
__device__ __forceinline__ void fma2(u64& d, u64 a, u64 b) {
    asm("fma.rn.f32x2 %0, %1, %2, %0;" : "+l"(d) : "l"(a), "l"(b));
}
__device__ __forceinline__ float2 unpack2(u64 v) {
    float2 r;
    asm("mov.b64 {%0, %1}, %2;" : "=f"(r.x), "=f"(r.y) : "l"(v));
    return r;
}
__device__ __forceinline__ u64 as_u64(float2 v) {
    u64 r;
    asm("mov.b64 %0, {%1, %2};" : "=l"(r) : "f"(v.x), "f"(v.y));
    return r;
}
// broadcast a shared-memory scalar into both lanes of an f32x2 register pair:
// two LDS of the same address into an aligned pair; mov.b64 {lo,hi} is elided
// by ptxas when lo/hi are allocated as the pair.
__device__ __forceinline__ u64 lds_bcast(unsigned int saddr) {
    u64 r;
    asm("{ .reg .f32 lo, hi;\n\t"
        "ld.shared.f32 lo, [%1];\n\t"
        "ld.shared.f32 hi, [%1];\n\t"
        "mov.b64 %0, {lo, hi}; }"
        : "=l"(r) : "r"(saddr));
    return r;
}

// ---- cp.async helpers ----------------------------------------------------
__device__ __forceinline__ void cp_async4(unsigned int smem_dst, const float* src) {
    asm volatile("cp.async.ca.shared.global [%0], [%1], 4;" :: "r"(smem_dst), "l"(src));
}
__device__ __forceinline__ void cp_async16(unsigned int smem_dst, const float* src) {
    asm volatile("cp.async.cg.shared.global [%0], [%1], 16;" :: "r"(smem_dst), "l"(src));
}
__device__ __forceinline__ void cp_commit()  { asm volatile("cp.async.commit_group;"); }
__device__ __forceinline__ void cp_wait1()   { asm volatile("cp.async.wait_group 1;"); }
__device__ __forceinline__ void cp_wait0()   { asm volatile("cp.async.wait_group 0;"); }

// ---------------------------------------------------------------------------
// Pass 1: avg_pool2d k=3 s=2 pad=1 (count_include_pad: always /9).
// ~84% DRAM — near unique-traffic roofline; unchanged from the champion.
// ---------------------------------------------------------------------------
__global__ __launch_bounds__(256) void pool_kernel(const float* __restrict__ feat) {
    int idx = blockIdx.x * 256 + threadIdx.x;
    int pwq = idx & 31;
    int t   = idx >> 5;
    int ph  = t & 127;
    int bc  = t >> 7;
    const float* src = feat + (size_t)bc * (Hn * Wn);
    int c0 = pwq << 3;

    float s0 = 0.f, s1 = 0.f, s2 = 0.f, s3 = 0.f;
    int rbase = 2 * ph - 1;
#pragma unroll
    for (int rr = 0; rr < 3; rr++) {
        int r = rbase + rr;
        if (r < 0) continue;
        const float* row = src + r * Wn;
        float left = (c0 > 0) ? __ldcs(row + c0 - 1) : 0.f;
        float4 a  = __ldcs(reinterpret_cast<const float4*>(row + c0));
        float4 b4 = __ldcs(reinterpret_cast<const float4*>(row + c0 + 4));
        s0 += left + a.x  + a.y;
        s1 += a.y  + a.z  + a.w;
        s2 += a.w  + b4.x + b4.y;
        s3 += b4.y + b4.z + b4.w;
    }
    const float inv9 = 1.0f / 9.0f;
    float4 o = make_float4(s0 * inv9, s1 * inv9, s2 * inv9, s3 * inv9);
    *reinterpret_cast<float4*>(g_pooled + (size_t)bc * PCH_STRIDE + ph * PWn + (pwq << 2)) = o;
}

// ---------------------------------------------------------------------------
// Pass 2: diff + fused P2. R15 champion structure with:
//   - RACE FIX: trailing __syncthreads() after compute — the next iteration's
//     stage into buffer 1-cur can no longer overlap laggards' reads of it.
//     (restores deterministic results; R5/R15 ordering had a WAR window)
//   - dual-LDS broadcast (lds_bcast) replaces LDS+2*MOV bcast2: hot loop
//     drops 44 -> 36 instr/channel.
// ---------------------------------------------------------------------------
#define CHUNK   4
#define HALO    324                 // 18*18
#define FROW    32                  // feature smem row (floats)
#define FCH     (32 * FROW)         // 1024 floats per staged channel
#define NITER   (Cn / CHUNK)        // 16

__global__ __launch_bounds__(256, 4) void diff_kernel(const float* __restrict__ feat,
                                                      float* __restrict__ out) {
    __shared__ __align__(16) float sfeat[2][CHUNK * FCH];  // 32,768 B
    __shared__ float shalo[2][CHUNK * HALO];               // 10,368 B
    __shared__ float sP2[HALO];                            //  1,296 B

    int b   = blockIdx.z;
    int ph0 = blockIdx.y << 4;
    int pw0 = blockIdx.x << 4;
    int tid = threadIdx.x;
    int qx  = tid & 15, qy = tid >> 4;

    const float* fimg = feat + (size_t)b * Cn * CH_STRIDE;
    const float* pimg = g_pooled + (size_t)b * Cn * PCH_STRIDE;
    unsigned int sfeat_a = (unsigned int)__cvta_generic_to_shared(&sfeat[0][0]);
    unsigned int shalo_a = (unsigned int)__cvta_generic_to_shared(&shalo[0][0]);

    // ---- feature staging constants: 1 cp16 per channel per thread ----
    int frow = tid >> 3;
    int fcol = (tid & 7) << 2;
    const float* fsrc0 = fimg + (size_t)((ph0 << 1) + frow) * Wn + (pw0 << 1) + fcol;
    unsigned int fdst0 = sfeat_a + (unsigned)(frow * FROW + fcol) * 4;

    // ---- halo staging descriptors, precomputed ONCE (6 slots) ----
    int hsrc[6];
    unsigned int hdst[6];
    bool hok[6];
#pragma unroll
    for (int u = 0; u < 6; u++) {
        int k = tid + 256 * u;
        hok[u] = (k < CHUNK * HALO);
        int kk = hok[u] ? k : 0;
        int c = kk / HALO;
        int r = kk - c * HALO;
        int i = r / 18;
        int j = r - i * 18;
        int gr = (ph0 - 1 + i) & 127;
        int gc = (pw0 - 1 + j) & 127;
        hsrc[u] = c * PCH_STRIDE + (gr << 7) + gc;
        hdst[u] = (unsigned)kk * 4;
    }

    // cc is a CHANNEL BASE
    auto stage = [&](int buf, int cc) {
        unsigned int fd = fdst0 + buf * (CHUNK * FCH * 4);
        const float* fs = fsrc0 + (size_t)cc * CH_STRIDE;
#pragma unroll
        for (int m = 0; m < CHUNK; m++) {
            cp_async16(fd + m * (FCH * 4), fs);
            fs += CH_STRIDE;
        }
        unsigned int hd = shalo_a + buf * (CHUNK * HALO * 4);
        const float* pb = pimg + (size_t)cc * PCH_STRIDE;
#pragma unroll
        for (int u = 0; u < 6; u++)
            if (hok[u]) cp_async4(hd + hdst[u], pb + hsrc[u]);
        cp_commit();
    };

    // ---- accumulators ----
    u64 z = 0;
    u64 cr01[8], cr23[8];
#pragma unroll
    for (int s = 0; s < 8; s++) { cr01[s] = z; cr23[s] = z; }
    u64 F2_01 = z, F2_23 = z;
    float p2acc0 = 0.f, p2acc1 = 0.f;
    int cell1 = tid + 256;
    bool has1 = (cell1 < HALO);
    int sbase = (qy + 1) * 18 + (qx + 1);
    int qoff  = (qy << 1) * FROW + (qx << 1);

    stage(0, 0);

    for (int it = 0; it < NITER; it++) {
        int cur = it & 1;
        if (it + 1 < NITER) { stage(1 - cur, (it + 1) * CHUNK); cp_wait1(); }
        else                { cp_wait0(); }
        __syncthreads();                    // sync_A: staged chunk visible

        const float* hbuf = &shalo[cur][0];
        const float* fbuf = &sfeat[cur][0];
        unsigned int hba = shalo_a + (unsigned)cur * (CHUNK * HALO * 4);

        // ---- P2 fold over the staged halo (register-carried) ----
#pragma unroll
        for (int c = 0; c < CHUNK; c++) {
            float v = hbuf[c * HALO + tid];
            p2acc0 += v * v;
        }
        if (has1) {
#pragma unroll
            for (int c = 0; c < CHUNK; c++) {
                float v = hbuf[c * HALO + cell1];
                p2acc1 += v * v;
            }
        }

        // ---- quad accumulation (dual-LDS broadcasts, zero bcast MOVs) ----
#pragma unroll
        for (int c = 0; c < CHUNK; c++) {
            const float* fp = fbuf + c * FCH + qoff;
            u64 f01 = as_u64(*reinterpret_cast<const float2*>(fp));
            u64 f23 = as_u64(*reinterpret_cast<const float2*>(fp + FROW));

            unsigned int hca = hba + (unsigned)(c * HALO + sbase) * 4;
            u64 pp0 = lds_bcast(hca - 19 * 4);
            u64 pp1 = lds_bcast(hca - 18 * 4);
            u64 pp2 = lds_bcast(hca - 17 * 4);
            u64 pp3 = lds_bcast(hca - 1 * 4);
            u64 pp4 = lds_bcast(hca + 1 * 4);
            u64 pp5 = lds_bcast(hca + 17 * 4);
            u64 pp6 = lds_bcast(hca + 18 * 4);
            u64 pp7 = lds_bcast(hca + 19 * 4);

            fma2(F2_01, f01, f01);
            fma2(F2_23, f23, f23);
            fma2(cr01[0], f01, pp0); fma2(cr23[0], f23, pp0);
            fma2(cr01[1], f01, pp1); fma2(cr23[1], f23, pp1);
            fma2(cr01[2], f01, pp2); fma2(cr23[2], f23, pp2);
            fma2(cr01[3], f01, pp3); fma2(cr23[3], f23, pp3);
            fma2(cr01[4], f01, pp4); fma2(cr23[4], f23, pp4);
            fma2(cr01[5], f01, pp5); fma2(cr23[5], f23, pp5);
            fma2(cr01[6], f01, pp6); fma2(cr23[6], f23, pp6);
            fma2(cr01[7], f01, pp7); fma2(cr23[7], f23, pp7);
        }

        __syncthreads();                    // sync_B (RACE FIX): all reads of
                                            // this chunk's buffers complete
                                            // before anyone stages into them
    }

    // ---- publish P2 tile ----
    sP2[tid] = p2acc0;
    if (has1) sP2[cell1] = p2acc1;
    __syncthreads();

    float P2n[8];
    P2n[0] = sP2[sbase - 19]; P2n[1] = sP2[sbase - 18]; P2n[2] = sP2[sbase - 17];
    P2n[3] = sP2[sbase - 1];                             P2n[4] = sP2[sbase + 1];
    P2n[5] = sP2[sbase + 17]; P2n[6] = sP2[sbase + 18]; P2n[7] = sP2[sbase + 19];

    float2 F2p01 = unpack2(F2_01);
    float2 F2p23 = unpack2(F2_23);
    float F2arr[4] = {F2p01.x, F2p01.y, F2p23.x, F2p23.y};

    float res[4] = {-3.4e38f, -3.4e38f, -3.4e38f, -3.4e38f};
#pragma unroll
    for (int s = 0; s < 8; s++) {
        float2 c01 = unpack2(cr01[s]);
        float2 c23 = unpack2(cr23[s]);
        res[0] = fmaxf(res[0], F2arr[0] - 2.f * c01.x + P2n[s]);
        res[1] = fmaxf(res[1], F2arr[1] - 2.f * c01.y + P2n[s]);
        res[2] = fmaxf(res[2], F2arr[2] - 2.f * c23.x + P2n[s]);
        res[3] = fmaxf(res[3], F2arr[3] - 2.f * c23.y + P2n[s]);
    }

    int ph = ph0 + qy, pw = pw0 + qx;
    float* orow = out + (size_t)b * (Hn * Wn) + (ph << 1) * Wn + (pw << 1);
    *reinterpret_cast<float2*>(orow)      = make_float2(res[0], res[1]);
    *reinterpret_cast<float2*>(orow + Wn) = make_float2(res[2], res[3]);
}

// ---------------------------------------------------------------------------
extern "C" void kernel_launch(void* const* d_in, const int* in_sizes, int n_in,
                              void* d_out, int out_size) {
    const float* feat = (const float*)d_in[0];
    float* out = (float*)d_out;
    // dist is fixed at 1 by the problem's setup_inputs (d = 2)

    pool_kernel<<<16384, 256>>>(feat);
    dim3 g(8, 8, Bn);
    diff_kernel<<<g, 256>>>(feat, out);
}